// round 3
// baseline (speedup 1.0000x reference)
#include <cuda_runtime.h>
#include <math.h>
#include <stdint.h>

#define NQ 75
#define NS 25
#define NU 64
#define NALL 164
#define H1 84
#define H2 42
#define H3 21
#define PP 441
#define KCLS 5
#define SHOT 5
#define MSUP (SHOT*PP)
#define MAUG (MSUP + 10*PP)
#define SELN 10
#define NEGINF -3.4e38f

__device__ float g_bufA[(size_t)NALL*64*H1*H1];
__device__ float g_bufC[(size_t)NALL*64*H2*H2];
__device__ float g_bufD[(size_t)NALL*64*H3*H3];
__device__ float g_bufE[(size_t)NALL*64*H3*H3];
__device__ float g_bufB[(size_t)NALL*64*H2*H2];
__device__ float g_ndesc[(size_t)NALL*PP*64];
__device__ float g_bank[(size_t)KCLS*MAUG*64];
__device__ float g_stats[3*64*2];
__device__ float g_partU[NU*KCLS*4];
__device__ float g_partQ[NQ*KCLS*4];
__device__ float g_simu[NU*KCLS];
__device__ int   g_selidx[KCLS*SELN];

__device__ __forceinline__ float* bufPtr(int s){
    switch(s){
        case 0: return g_bufA; case 1: return g_bufB; case 2: return g_bufC;
        case 3: return g_bufD; default: return g_bufE;
    }
}
__device__ __forceinline__ int groupOf(int n){ return (n < NQ) ? 0 : ((n < NQ+NS) ? 1 : 2); }

// ---------- conv1: 3->64, 84x84 SAME ----------
__global__ void conv1_kernel(const float* __restrict__ in1, const float* __restrict__ in2,
                             const float* __restrict__ in3, const float* __restrict__ w)
{
    __shared__ float sW[64*27];
    __shared__ float sIn[3*18*18];
    const int n = blockIdx.z;
    const int gx0 = blockIdx.x*16, gy0 = blockIdx.y*16;
    const int tx = threadIdx.x, ty = threadIdx.y;
    const int tid = ty*16 + tx;
    const float* img = (n < NQ)    ? (in1 + (size_t)n*3*H1*H1)
                     : (n < NQ+NS) ? (in2 + (size_t)(n-NQ)*3*H1*H1)
                                   : (in3 + (size_t)(n-NQ-NS)*3*H1*H1);
    for (int i = tid; i < 64*27; i += 256) sW[i] = w[i];
    for (int i = tid; i < 3*18*18; i += 256) {
        int c = i / 324, rem = i % 324, r = rem/18, cc = rem%18;
        int gy = gy0 - 1 + r, gx = gx0 - 1 + cc;
        sIn[i] = (gy>=0 && gy<H1 && gx>=0 && gx<H1) ? img[((size_t)c*H1+gy)*H1+gx] : 0.f;
    }
    __syncthreads();
    int ox = gx0+tx, oy = gy0+ty;
    if (ox >= H1 || oy >= H1) return;
    float v[27];
#pragma unroll
    for (int c=0;c<3;c++)
#pragma unroll
      for (int dy=0;dy<3;dy++)
#pragma unroll
        for (int dx=0;dx<3;dx++)
          v[c*9+dy*3+dx] = sIn[c*324 + (ty+dy)*18 + (tx+dx)];
#pragma unroll 4
    for (int oc=0; oc<64; oc++){
        float acc = 0.f;
        const float* wp = sW + oc*27;
#pragma unroll
        for (int j=0;j<27;j++) acc += wp[j]*v[j];
        g_bufA[(((size_t)n*64+oc)*H1+oy)*H1+ox] = acc;
    }
}

// ---------- conv 64->64 3x3 SAME ----------
template<int RPT>
__global__ void conv64_kernel(int inSel, int outSel, const float* __restrict__ wt, int H, int W)
{
    extern __shared__ float sm[];
    float* sW  = sm;
    float* sIn = sm + 36864;
    constexpr int TH   = 16*RPT;
    constexpr int HALO = (TH+2)*18;
    const int n   = blockIdx.z;
    const int gx0 = blockIdx.x*16;
    const int gy0 = blockIdx.y*TH;
    const int tx = threadIdx.x, ty = threadIdx.y;
    const int tid = ty*16 + tx;
    for (int i = tid; i < 64*64*9; i += 256) sW[i] = wt[i];
    const int oyb = gy0 + ty*RPT;
    const int ox  = gx0 + tx;
    const bool anyValid = (ox < W) && (oyb < H);
    const float* inN  = bufPtr(inSel)  + (size_t)n*64*H*W;
    float*       outN = bufPtr(outSel) + (size_t)n*64*H*W;

    for (int ocg = 0; ocg < 4; ++ocg) {
        float acc[16][RPT];
#pragma unroll
        for (int o=0;o<16;o++)
#pragma unroll
          for (int r=0;r<RPT;r++) acc[o][r]=0.f;
        for (int cc = 0; cc < 4; ++cc) {
            __syncthreads();
            for (int i = tid; i < 16*HALO; i += 256) {
                int c = i / HALO, rem = i % HALO, r = rem/18, col = rem%18;
                int gy = gy0-1+r, gx = gx0-1+col;
                float v = 0.f;
                if (gy>=0 && gy<H && gx>=0 && gx<W)
                    v = inN[((size_t)(cc*16+c)*H+gy)*W+gx];
                sIn[i] = v;
            }
            __syncthreads();
            if (anyValid) {
                for (int ic=0; ic<16; ++ic) {
                    float v[RPT+2][3];
                    const float* sp = sIn + ic*HALO + (ty*RPT)*18 + tx;
#pragma unroll
                    for (int r=0;r<RPT+2;r++)
#pragma unroll
                      for (int d=0;d<3;d++) v[r][d] = sp[r*18+d];
                    const float* wp = sW + (size_t)(ocg*16)*576 + (cc*16+ic)*9;
#pragma unroll
                    for (int o=0;o<16;o++){
                        const float* wo = wp + o*576;
                        float w0=wo[0],w1=wo[1],w2=wo[2],w3=wo[3],w4=wo[4];
                        float w5=wo[5],w6=wo[6],w7=wo[7],w8=wo[8];
#pragma unroll
                        for (int r=0;r<RPT;r++){
                            float a = acc[o][r];
                            a += w0*v[r  ][0]; a += w1*v[r  ][1]; a += w2*v[r  ][2];
                            a += w3*v[r+1][0]; a += w4*v[r+1][1]; a += w5*v[r+1][2];
                            a += w6*v[r+2][0]; a += w7*v[r+2][1]; a += w8*v[r+2][2];
                            acc[o][r] = a;
                        }
                    }
                }
            }
        }
        if (anyValid) {
#pragma unroll
            for (int o=0;o<16;o++){
                int oc = ocg*16+o;
#pragma unroll
                for (int r=0;r<RPT;r++){
                    int oy = oyb + r;
                    if (oy < H) outN[((size_t)oc*H+oy)*W+ox] = acc[o][r];
                }
            }
        }
    }
}

// ---------- BN stats (training mode, per feature-extractor call group) ----------
__global__ void bn_stats_kernel(int sel, int HW)
{
    __shared__ double ssum[256], ssum2[256];
    const int ch = blockIdx.x, g = blockIdx.y;
    const int n0 = (g==0)?0:((g==1)?NQ:(NQ+NS));
    const int n1 = (g==0)?NQ:((g==1)?(NQ+NS):NALL);
    const int tid = threadIdx.x;
    const float* buf = bufPtr(sel);
    double s=0.0, s2=0.0;
    for (int n=n0; n<n1; ++n) {
        const float* p = buf + ((size_t)n*64+ch)*HW;
        for (int i=tid;i<HW;i+=256){ double x = (double)p[i]; s+=x; s2+=x*x; }
    }
    ssum[tid]=s; ssum2[tid]=s2; __syncthreads();
    for (int st=128; st>0; st>>=1){
        if (tid<st){ ssum[tid]+=ssum[tid+st]; ssum2[tid]+=ssum2[tid+st]; }
        __syncthreads();
    }
    if (tid==0){
        double cnt = (double)(n1-n0)*HW;
        double mean = ssum[0]/cnt;
        double var  = ssum2[0]/cnt - mean*mean;
        g_stats[(g*64+ch)*2+0] = (float)mean;
        g_stats[(g*64+ch)*2+1] = (float)(1.0/sqrt(var + 1e-5));
    }
}

// ---------- BN + LeakyReLU (+ optional 2x2 maxpool) ----------
__global__ void bn_pool_kernel(int inSel, int outSel, const float* __restrict__ gamma,
                               const float* __restrict__ beta, int H, int W, int doPool)
{
    const int oH = doPool ? H/2 : H, oW = doPool ? W/2 : W;
    const size_t total = (size_t)NALL*64*oH*oW;
    const float* in = bufPtr(inSel);
    float* out = bufPtr(outSel);
    for (size_t idx = (size_t)blockIdx.x*blockDim.x + threadIdx.x; idx < total;
         idx += (size_t)gridDim.x*blockDim.x) {
        int ox = (int)(idx % oW); size_t t = idx / oW;
        int oy = (int)(t % oH);   t /= oH;
        int c  = (int)(t % 64);   int n = (int)(t / 64);
        int g = groupOf(n);
        float mean = g_stats[(g*64+c)*2+0], rsig = g_stats[(g*64+c)*2+1];
        float sc = gamma[c]*rsig;
        float sh = beta[c] - mean*sc;
        const float* p = in + ((size_t)n*64+c)*H*W;
        float r;
        if (doPool){
            float x0 = p[(size_t)(2*oy)*W + 2*ox  ]*sc+sh;
            float x1 = p[(size_t)(2*oy)*W + 2*ox+1]*sc+sh;
            float x2 = p[(size_t)(2*oy+1)*W + 2*ox  ]*sc+sh;
            float x3 = p[(size_t)(2*oy+1)*W + 2*ox+1]*sc+sh;
            x0 = x0>=0.f?x0:0.2f*x0; x1 = x1>=0.f?x1:0.2f*x1;
            x2 = x2>=0.f?x2:0.2f*x2; x3 = x3>=0.f?x3:0.2f*x3;
            r = fmaxf(fmaxf(x0,x1), fmaxf(x2,x3));
        } else {
            float x = p[(size_t)oy*W+ox]*sc+sh;
            r = x>=0.f?x:0.2f*x;
        }
        out[idx] = r;
    }
}

// ---------- normalized descriptors [img][p][c] ----------
__global__ void ndesc_kernel()
{
    int idx = blockIdx.x*blockDim.x + threadIdx.x;
    if (idx >= NALL*PP) return;
    int n = idx / PP, p = idx % PP;
    const float* f = g_bufD + (size_t)n*64*PP + p;
    float vals[64]; float ss = 0.f;
#pragma unroll
    for (int c=0;c<64;c++){ float x = f[(size_t)c*PP]; vals[c]=x; ss += x*x; }
    float rinv = 1.0f/sqrtf(ss);
    float* o = g_ndesc + (size_t)idx*64;
#pragma unroll
    for (int c=0;c<64;c++) o[c] = vals[c]*rinv;
}

// ---------- bank fills ----------
__global__ void fill_support_kernel()
{
    const size_t total = (size_t)KCLS*MSUP*64;
    for (size_t i = (size_t)blockIdx.x*blockDim.x + threadIdx.x; i < total;
         i += (size_t)gridDim.x*blockDim.x) {
        int k = (int)(i & 63); size_t t = i >> 6;
        int col = (int)(t % MSUP); int j = (int)(t / MSUP);
        int s = col / PP, p = col % PP;
        int img = NQ + j*SHOT + s;
        g_bank[((size_t)j*MAUG + col)*64 + k] = g_ndesc[((size_t)img*PP + p)*64 + k];
    }
}
__global__ void fill_aug_kernel()
{
    const size_t total = (size_t)KCLS*(SELN*PP)*64;
    for (size_t i = (size_t)blockIdx.x*blockDim.x + threadIdx.x; i < total;
         i += (size_t)gridDim.x*blockDim.x) {
        int k = (int)(i & 63); size_t t = i >> 6;
        int col = (int)(t % (SELN*PP)); int j = (int)(t / (SELN*PP));
        int sel = col / PP, p = col % PP;
        int img = NQ + NS + g_selidx[j*SELN + sel];
        g_bank[((size_t)j*MAUG + MSUP + col)*64 + k] = g_ndesc[((size_t)img*PP + p)*64 + k];
    }
}

// ---------- top-3-fused GEMM: grid(4, KCLS, nImg), block(16,16) ----------
__global__ void topk_gemm_kernel(int img_base, int cols, int partSel)
{
    extern __shared__ float sm[];
    float* As = sm;
    float* Bs = sm + 8320;
    const int tx = threadIdx.x, ty = threadIdx.y;
    const int tid = ty*16 + tx;
    const int cls = blockIdx.y;
    const int imgL = blockIdx.z;
    const int img = img_base + imgL;
    const int row0 = blockIdx.x*128;

    for (int i=tid; i<8192; i+=256){
        int r = i>>6, k = i&63;
        int p = row0 + r;
        As[r*65+k] = (p < PP) ? g_ndesc[((size_t)img*PP + p)*64 + k] : 0.f;
    }
    float t0[8], t1[8], t2[8];
#pragma unroll
    for (int r=0;r<8;r++){ t0[r]=NEGINF; t1[r]=NEGINF; t2[r]=NEGINF; }
    const float* bankC = g_bank + (size_t)cls*MAUG*64;
    const int ntiles = (cols + 127)/128;

    for (int t=0; t<ntiles; t++){
        const int col0 = t*128;
        __syncthreads();
        for (int i=tid; i<8192; i+=256){
            int c = i>>6, k = i&63;
            int col = col0 + c;
            Bs[c*65+k] = (col < cols) ? bankC[(size_t)col*64 + k] : 0.f;
        }
        __syncthreads();
        float acc[8][8];
#pragma unroll
        for (int r=0;r<8;r++)
#pragma unroll
          for (int c=0;c<8;c++) acc[r][c]=0.f;
#pragma unroll 4
        for (int k=0;k<64;k++){
            float a[8], b[8];
#pragma unroll
            for (int r=0;r<8;r++) a[r] = As[(r*16+ty)*65 + k];
#pragma unroll
            for (int c=0;c<8;c++) b[c] = Bs[(c*16+tx)*65 + k];
#pragma unroll
            for (int r=0;r<8;r++)
#pragma unroll
              for (int c=0;c<8;c++) acc[r][c] += a[r]*b[c];
        }
#pragma unroll
        for (int c=0;c<8;c++){
            int colg = col0 + c*16 + tx;
            bool ok = colg < cols;
#pragma unroll
            for (int r=0;r<8;r++){
                float v = ok ? acc[r][c] : NEGINF;
                if (v > t2[r]) {
                    if (v > t0[r]) { t2[r]=t1[r]; t1[r]=t0[r]; t0[r]=v; }
                    else if (v > t1[r]) { t2[r]=t1[r]; t1[r]=v; }
                    else t2[r]=v;
                }
            }
        }
    }
    __syncthreads();
    float* M = sm;       // [128 rows][16 lanes][3]
#pragma unroll
    for (int r=0;r<8;r++){
        int row = r*16 + ty;
        M[(row*16+tx)*3+0] = t0[r];
        M[(row*16+tx)*3+1] = t1[r];
        M[(row*16+tx)*3+2] = t2[r];
    }
    __syncthreads();
    float* P = sm + 8320;
    if (tid < 128){
        float u0=NEGINF, u1=NEGINF, u2=NEGINF;
        const float* m = M + (size_t)tid*48;
        for (int j=0;j<48;j++){
            float v = m[j];
            if (v > u2){
                if (v > u0){ u2=u1; u1=u0; u0=v; }
                else if (v > u1){ u2=u1; u1=v; }
                else u2=v;
            }
        }
        P[tid] = (row0 + tid < PP) ? (u0+u1+u2) : 0.f;
    }
    __syncthreads();
    for (int st=64; st>0; st>>=1){
        if (tid < st) P[tid] += P[tid+st];
        __syncthreads();
    }
    if (tid==0){
        float* part = (partSel == 0) ? g_partU : g_partQ;
        part[((size_t)imgL*KCLS + cls)*4 + blockIdx.x] = P[0];
    }
}

// ---------- deterministic 4-way reduce ----------
__global__ void reduce4_kernel(int sel, float* __restrict__ outp, int n)
{
    int i = blockIdx.x*blockDim.x + threadIdx.x;
    if (i >= n) return;
    const float* part = (sel == 0) ? g_partU : g_partQ;
    float* out = (sel == 0) ? g_simu : outp;
    out[i] = part[4*i] + part[4*i+1] + part[4*i+2] + part[4*i+3];
}

// ---------- softmax + per-class top-10 (lowest-index tie break) ----------
__global__ void select_kernel()
{
    __shared__ float pm[NU*KCLS];
    int tid = threadIdx.x;
    if (tid < NU){
        float v[KCLS]; float mx = NEGINF;
#pragma unroll
        for (int j=0;j<KCLS;j++){ v[j] = g_simu[tid*KCLS+j]; mx = fmaxf(mx, v[j]); }
        float s = 0.f;
#pragma unroll
        for (int j=0;j<KCLS;j++){ v[j] = expf(v[j]-mx); s += v[j]; }
#pragma unroll
        for (int j=0;j<KCLS;j++) pm[tid*KCLS+j] = v[j]/s;
    }
    __syncthreads();
    if (tid < KCLS){
        unsigned long long taken = 0ull;
        for (int i=0;i<SELN;i++){
            float best = NEGINF; int bi = 0;
            for (int b=0;b<NU;b++){
                if (taken & (1ull<<b)) continue;
                float val = pm[b*KCLS+tid];
                if (val > best){ best = val; bi = b; }
            }
            taken |= (1ull<<bi);
            g_selidx[tid*SELN+i] = bi;
        }
    }
}

extern "C" void kernel_launch(void* const* d_in, const int* in_sizes, int n_in,
                              void* d_out, int out_size)
{
    (void)in_sizes; (void)n_in; (void)out_size;
    // metadata order follows setup_inputs() dict insertion order:
    // input1, input2, input3, w1, w2, w3, w4, g1, b1, g2, b2, g3, b3, g4, b4
    const float* in1 = (const float*)d_in[0];
    const float* in2 = (const float*)d_in[1];
    const float* in3 = (const float*)d_in[2];
    const float* w1  = (const float*)d_in[3];
    const float* w2  = (const float*)d_in[4];
    const float* w3  = (const float*)d_in[5];
    const float* w4  = (const float*)d_in[6];
    const float* gg1 = (const float*)d_in[7];
    const float* bb1 = (const float*)d_in[8];
    const float* gg2 = (const float*)d_in[9];
    const float* bb2 = (const float*)d_in[10];
    const float* gg3 = (const float*)d_in[11];
    const float* bb3 = (const float*)d_in[12];
    const float* gg4 = (const float*)d_in[13];
    const float* bb4 = (const float*)d_in[14];
    float* out = (float*)d_out;

    const int SM3 = (36864 + 16*(50*18))*4;   // conv64<3>: 205056 B
    const int SM2 = (36864 + 16*(34*18))*4;   // conv64<2>: 186624 B
    const int SMG = 2*8320*4;                 // topk:       66560 B
    cudaFuncSetAttribute(conv64_kernel<3>, cudaFuncAttributeMaxDynamicSharedMemorySize, SM3);
    cudaFuncSetAttribute(conv64_kernel<2>, cudaFuncAttributeMaxDynamicSharedMemorySize, SM2);
    cudaFuncSetAttribute(topk_gemm_kernel,  cudaFuncAttributeMaxDynamicSharedMemorySize, SMG);

    dim3 blk(16,16);
    // layer 1
    conv1_kernel<<<dim3(6,6,NALL), blk>>>(in1, in2, in3, w1);
    bn_stats_kernel<<<dim3(64,3), 256>>>(0, H1*H1);
    bn_pool_kernel<<<2048, 256>>>(0, 1, gg1, bb1, H1, H1, 1);       // A -> B (42)
    // layer 2
    conv64_kernel<3><<<dim3(3,1,NALL), blk, SM3>>>(1, 2, w2, H2, H2); // B -> C
    bn_stats_kernel<<<dim3(64,3), 256>>>(2, H2*H2);
    bn_pool_kernel<<<2048, 256>>>(2, 3, gg2, bb2, H2, H2, 1);       // C -> D (21)
    // layer 3
    conv64_kernel<2><<<dim3(2,1,NALL), blk, SM2>>>(3, 4, w3, H3, H3); // D -> E
    bn_stats_kernel<<<dim3(64,3), 256>>>(4, H3*H3);
    bn_pool_kernel<<<2048, 256>>>(4, 3, gg3, bb3, H3, H3, 0);       // E -> D
    // layer 4
    conv64_kernel<2><<<dim3(2,1,NALL), blk, SM2>>>(3, 4, w4, H3, H3); // D -> E
    bn_stats_kernel<<<dim3(64,3), 256>>>(4, H3*H3);
    bn_pool_kernel<<<2048, 256>>>(4, 3, gg4, bb4, H3, H3, 0);       // E -> D (final feats)

    ndesc_kernel<<<(NALL*PP + 255)/256, 256>>>();
    fill_support_kernel<<<2048, 256>>>();

    // stage 1: unlabeled vs support banks
    topk_gemm_kernel<<<dim3(4,KCLS,NU), blk, SMG>>>(NQ+NS, MSUP, 0);
    reduce4_kernel<<<(NU*KCLS + 255)/256, 256>>>(0, nullptr, NU*KCLS);
    select_kernel<<<1, 64>>>();
    fill_aug_kernel<<<2048, 256>>>();

    // stage 2: queries vs augmented banks -> output [75,5]
    topk_gemm_kernel<<<dim3(4,KCLS,NQ), blk, SMG>>>(0, MAUG, 1);
    reduce4_kernel<<<(NQ*KCLS + 255)/256, 256>>>(1, out, NQ*KCLS);
}